// round 14
// baseline (speedup 1.0000x reference)
#include <cuda_runtime.h>

// FINAL (locked; best-measured config, reproduced R9-R13:
// kernel 4.83-5.25us, total 6.62-6.88us = fixed floor ± ~0.25us jitter).
//
// out[i] = cos(x[i]) — analytical collapse of the 4-wire / 4-layer
// RY-RZ-CNOT circuit:
//   * RZ layers are diagonal unit-modulus phases -> |amplitude|^2 unchanged;
//     the output depends only on probabilities.
//   * The CNOT chain 0->1, 1->2, 2->3 acts on basis-index bits as the GF(2)
//     linear map T (lower-triangular all-ones). T^2 = I + S2 (shift-by-2),
//     so T^4 = I + S2^2 = I in 4 dims: after 4 layers the basis permutation
//     is the identity.
//   * Probabilities remain the initial RY product state:
//     <Z_w> = cos^2(x_w/2) - sin^2(x_w/2) = cos(x_w). weights are unused.
//
// Perf conclusion (13 rounds, GB300 sm_103a): eight body variants — libm
// cosf, MUFU ILP1/2/4, TMA cp.async.bulk pipeline, streaming stores, 256-bit
// LDG/STG — all land at 6.6-6.9us total while ncu kernel time varies
// 4.8-5.7us with zero correlation to the total. All pipes <= 11% of peak.
// The benchmark is pinned at the fixed graph-replay + launch-overhead
// (T_ovh ~5000 cyc) floor; the 8 MB of LTS traffic is a minor additive term.
// Best-measured configuration:
//   - ILP=2 float4/thread, front-batched LDG.128 x2 (MLP=2)
//   - 512 blocks x 256 threads
//   - MUFU.COS (__cosf): abs err ~2^-21 on N(0,1) inputs, rel_err 2.2e-7
//   - __stcs evict-first streaming stores: write-only output doesn't evict
//     the L2-resident input across graph replays.

__global__ void __launch_bounds__(256) qk_cos_final(const float4* __restrict__ x,
                                                    float4* __restrict__ out, int n4) {
    int i = (blockIdx.x * blockDim.x + threadIdx.x) * 2;
    if (i + 1 < n4) {
        // front-batch both 128-bit loads (MLP=2)
        float4 v0 = x[i];
        float4 v1 = x[i + 1];
        float4 r0, r1;
        r0.x = __cosf(v0.x); r0.y = __cosf(v0.y);
        r0.z = __cosf(v0.z); r0.w = __cosf(v0.w);
        r1.x = __cosf(v1.x); r1.y = __cosf(v1.y);
        r1.z = __cosf(v1.z); r1.w = __cosf(v1.w);
        __stcs(&out[i],     r0);
        __stcs(&out[i + 1], r1);
    } else if (i < n4) {
        float4 v0 = x[i];
        float4 r0;
        r0.x = __cosf(v0.x); r0.y = __cosf(v0.y);
        r0.z = __cosf(v0.z); r0.w = __cosf(v0.w);
        __stcs(&out[i], r0);
    }
}

// Safety net for element counts not divisible by 4 (never launched for this
// problem's shape, so it adds no graph nodes).
__global__ void qk_cos_tail(const float* __restrict__ x, float* __restrict__ out,
                            int start, int n) {
    int i = start + blockIdx.x * blockDim.x + threadIdx.x;
    if (i < n) out[i] = __cosf(x[i]);
}

extern "C" void kernel_launch(void* const* d_in, const int* in_sizes, int n_in,
                              void* d_out, int out_size) {
    const float* x = (const float*)d_in[0];   // (262144, 4) float32
    float* out = (float*)d_out;
    int n = out_size;          // 1,048,576
    int n4 = n >> 2;           // 262,144 float4s

    const int T = 256;
    int threads_needed = (n4 + 1) >> 1;        // ILP=2
    int blocks = (threads_needed + T - 1) / T; // 512
    qk_cos_final<<<blocks, T>>>((const float4*)x, (float4*)out, n4);

    int rem = n - (n4 << 2);
    if (rem > 0) qk_cos_tail<<<1, 32>>>(x, out, n4 << 2, n);
}

// round 15
// speedup vs baseline: 1.0435x; 1.0435x over previous
#include <cuda_runtime.h>

// FINAL (locked; best-measured config, reproduced R9-R14:
// kernel 4.83-5.25us, total 6.62-6.91us = fixed floor ± ~0.25us jitter).
//
// out[i] = cos(x[i]) — analytical collapse of the 4-wire / 4-layer
// RY-RZ-CNOT circuit:
//   * RZ layers are diagonal unit-modulus phases -> |amplitude|^2 unchanged;
//     the output depends only on probabilities.
//   * The CNOT chain 0->1, 1->2, 2->3 acts on basis-index bits as the GF(2)
//     linear map T (lower-triangular all-ones). T^2 = I + S2 (shift-by-2),
//     so T^4 = I + S2^2 = I in 4 dims: after 4 layers the basis permutation
//     is the identity.
//   * Probabilities remain the initial RY product state:
//     <Z_w> = cos^2(x_w/2) - sin^2(x_w/2) = cos(x_w). weights are unused.
//
// Perf conclusion (14 rounds, GB300 sm_103a): eight body variants — libm
// cosf, MUFU ILP1/2/4, TMA cp.async.bulk pipeline, streaming stores, 256-bit
// LDG/STG — all land at 6.6-6.9us total while ncu kernel time varies
// 4.8-5.7us with zero correlation to the total. All pipes <= 11% of peak.
// The benchmark is pinned at the fixed graph-replay + launch-overhead
// (T_ovh ~5000 cyc) floor; the 8 MB of LTS traffic is a minor additive term.
// Best-measured configuration:
//   - ILP=2 float4/thread, front-batched LDG.128 x2 (MLP=2)
//   - 512 blocks x 256 threads
//   - MUFU.COS (__cosf): abs err ~2^-21 on N(0,1) inputs, rel_err 2.2e-7
//   - __stcs evict-first streaming stores: write-only output doesn't evict
//     the L2-resident input across graph replays.

__global__ void __launch_bounds__(256) qk_cos_final(const float4* __restrict__ x,
                                                    float4* __restrict__ out, int n4) {
    int i = (blockIdx.x * blockDim.x + threadIdx.x) * 2;
    if (i + 1 < n4) {
        // front-batch both 128-bit loads (MLP=2)
        float4 v0 = x[i];
        float4 v1 = x[i + 1];
        float4 r0, r1;
        r0.x = __cosf(v0.x); r0.y = __cosf(v0.y);
        r0.z = __cosf(v0.z); r0.w = __cosf(v0.w);
        r1.x = __cosf(v1.x); r1.y = __cosf(v1.y);
        r1.z = __cosf(v1.z); r1.w = __cosf(v1.w);
        __stcs(&out[i],     r0);
        __stcs(&out[i + 1], r1);
    } else if (i < n4) {
        float4 v0 = x[i];
        float4 r0;
        r0.x = __cosf(v0.x); r0.y = __cosf(v0.y);
        r0.z = __cosf(v0.z); r0.w = __cosf(v0.w);
        __stcs(&out[i], r0);
    }
}

// Safety net for element counts not divisible by 4 (never launched for this
// problem's shape, so it adds no graph nodes).
__global__ void qk_cos_tail(const float* __restrict__ x, float* __restrict__ out,
                            int start, int n) {
    int i = start + blockIdx.x * blockDim.x + threadIdx.x;
    if (i < n) out[i] = __cosf(x[i]);
}

extern "C" void kernel_launch(void* const* d_in, const int* in_sizes, int n_in,
                              void* d_out, int out_size) {
    const float* x = (const float*)d_in[0];   // (262144, 4) float32
    float* out = (float*)d_out;
    int n = out_size;          // 1,048,576
    int n4 = n >> 2;           // 262,144 float4s

    const int T = 256;
    int threads_needed = (n4 + 1) >> 1;        // ILP=2
    int blocks = (threads_needed + T - 1) / T; // 512
    qk_cos_final<<<blocks, T>>>((const float4*)x, (float4*)out, n4);

    int rem = n - (n4 << 2);
    if (rem > 0) qk_cos_tail<<<1, 32>>>(x, out, n4 << 2, n);
}